// round 3
// baseline (speedup 1.0000x reference)
#include <cuda_runtime.h>
#include <math.h>

#define BB 512
#define HH 1024
#define SS 1024
#define DD 128
#define KK 32

#define S1_GEMM 128
#define S1_COPY 1024
#define S2_LOG  128
#define S2_COPY 1024
#define S3_FRONT 512
#define S3_COPY 2048

// scratch (no allocations allowed)
__device__ float g_gate[BB];
__device__ float g_value[BB * DD];
__device__ float g_q[BB * DD];
__device__ float g_logits[BB * SS];
__device__ float g_topw[BB * KK];
__device__ int   g_topi[BB * KK];

// ---- streaming copy slice: one block moves 4096 float4 (64KB) ----
__device__ __forceinline__ void copy_slice(const float* __restrict__ memory,
                                           float* __restrict__ out, size_t blk)
{
    const int t = threadIdx.x;
    const size_t base = blk * 4096 + t;
    const float4* s4 = (const float4*)memory;
    float4* o4 = (float4*)(out + (size_t)BB * DD);
    float4 v[16];
    #pragma unroll
    for (int k = 0; k < 16; k++) v[k] = __ldcs(&s4[base + (size_t)k * 256]);
    #pragma unroll
    for (int k = 0; k < 16; k++) __stcs(&o4[base + (size_t)k * 256], v[k]);
}

// ================= stage 1: q & value GEMMs + copy A =================
__global__ void __launch_bounds__(256)
amt_stage1(const float* __restrict__ latent, const float* __restrict__ memory,
           const float* __restrict__ rqw, const float* __restrict__ rqb,
           const float* __restrict__ wvw, const float* __restrict__ wvb,
           float* __restrict__ out)
{
    extern __shared__ float sp[];
    if (blockIdx.x >= S1_GEMM) {
        copy_slice(memory, out, (size_t)(blockIdx.x - S1_GEMM));
        return;
    }
    const int t = threadIdx.x, w = t >> 5, lane = t & 31;
    const int wsel = blockIdx.x & 1;
    const int b0 = (blockIdx.x >> 1) * 8;
    const float* W    = wsel ? wvw : rqw;
    const float* bias = wsel ? wvb : rqb;
    float* OUT        = wsel ? g_value : g_q;

    float latreg[8][4];
    #pragma unroll
    for (int b = 0; b < 8; b++)
        #pragma unroll
        for (int r = 0; r < 4; r++)
            latreg[b][r] = latent[(size_t)(b0 + b) * HH + w * 128 + r * 32 + lane];

    const float4* W4 = (const float4*)W;
    float4 acc[8];
    #pragma unroll
    for (int b = 0; b < 8; b++) acc[b] = make_float4(0.f, 0.f, 0.f, 0.f);
    #pragma unroll
    for (int r = 0; r < 4; r++) {
        #pragma unroll 8
        for (int i = 0; i < 32; i++) {
            float4 wv = W4[(size_t)(w * 128 + r * 32 + i) * 32 + lane];
            #pragma unroll
            for (int b = 0; b < 8; b++) {
                float a = __shfl_sync(0xffffffffu, latreg[b][r], i);
                acc[b].x += a * wv.x; acc[b].y += a * wv.y;
                acc[b].z += a * wv.z; acc[b].w += a * wv.w;
            }
        }
    }
    #pragma unroll
    for (int b = 0; b < 8; b++)
        *(float4*)&sp[(w * 8 + b) * DD + lane * 4] = acc[b];
    __syncthreads();
    #pragma unroll
    for (int i = 0; i < 4; i++) {
        int o = t + i * 256;
        int b = o >> 7, d = o & 127;
        float s = bias[d];
        #pragma unroll
        for (int ww = 0; ww < 8; ww++) s += sp[(ww * 8 + b) * DD + d];
        OUT[(size_t)(b0 + b) * DD + d] = s;
    }
}

// ================= stage 2: logits GEMM + copy B =================
__global__ void __launch_bounds__(256)
amt_stage2(const float* __restrict__ memory, const float* __restrict__ mkey,
           float* __restrict__ out)
{
    extern __shared__ float sp[];
    if (blockIdx.x >= S2_LOG) {
        copy_slice(memory, out, (size_t)S1_COPY + (blockIdx.x - S2_LOG));
        return;
    }
    const int t = threadIdx.x;
    const int b0 = (blockIdx.x >> 2) * 16;
    const int s0 = (blockIdx.x & 3) * 256;
    float* qs = sp;          // 16*128 floats
    float* ks = sp + 2048;   // 256 rows * 20 floats (padded)

    {
        const float4* q4 = (const float4*)g_q;
        float4* qs4 = (float4*)qs;
        #pragma unroll
        for (int i = 0; i < 2; i++) {
            int p = t + i * 256;
            qs4[p] = q4[(size_t)b0 * 32 + p];
        }
    }
    float acc[16];
    #pragma unroll
    for (int b = 0; b < 16; b++) acc[b] = 0.f;
    const float4* K4 = (const float4*)mkey;
    for (int c = 0; c < 8; c++) {
        __syncthreads();
        #pragma unroll
        for (int i = 0; i < 4; i++) {
            int idx = t + i * 256;
            int row = idx >> 2, j = idx & 3;
            float4 kv = K4[(size_t)(s0 + row) * 32 + c * 4 + j];
            *(float4*)&ks[row * 20 + j * 4] = kv;
        }
        __syncthreads();
        #pragma unroll
        for (int j = 0; j < 4; j++) {
            float4 k4 = *(float4*)&ks[t * 20 + j * 4];
            #pragma unroll
            for (int b = 0; b < 16; b++) {
                float4 q4 = *(const float4*)&qs[b * DD + c * 16 + j * 4];
                acc[b] += k4.x * q4.x + k4.y * q4.y + k4.z * q4.z + k4.w * q4.w;
            }
        }
    }
    #pragma unroll
    for (int b = 0; b < 16; b++)
        g_logits[(size_t)(b0 + b) * SS + s0 + t] = acc[b];
}

// ====== stage 3: per-batch topk + scatter + gather + gate + copy C ======
__global__ void __launch_bounds__(256)
amt_stage3(const float* __restrict__ latent, const float* __restrict__ memory,
           const float* __restrict__ wgw, const float* __restrict__ wgb,
           const float* __restrict__ dmw, const float* __restrict__ dmb,
           const float* __restrict__ phw, const float* __restrict__ phb,
           float* __restrict__ out)
{
    extern __shared__ float sp[];
    if (blockIdx.x >= S3_FRONT) {
        copy_slice(memory, out, (size_t)(S1_COPY + S2_COPY) + (blockIdx.x - S3_FRONT));
        return;
    }
    const int t = threadIdx.x, lane = t & 31;
    const int b = blockIdx.x;
    float* lrow = sp;                 // 1024
    float* topw = sp + 1024;          // 32
    int*   topi = (int*)(sp + 1056);  // 32
    float* r2   = sp + 1088;          // 256

    float* out_read = out;
    float* out_wts  = out + (size_t)BB * DD + (size_t)BB * SS * DD;

    {   // load logits row + zero weights row
        const float4* l4 = (const float4*)g_logits;
        ((float4*)lrow)[t] = l4[(size_t)b * 256 + t];
        ((float4*)(out_wts + (size_t)b * SS))[t] = make_float4(0.f, 0.f, 0.f, 0.f);
    }
    __syncthreads();

    // ---- top-32 + renormalized weights (warp 0) ----
    if (t < 32) {
        float lmax = -INFINITY; int lidx = 0x7fffffff;
        #pragma unroll 4
        for (int j = 0; j < 32; j++) {
            float v = lrow[j * 32 + lane];
            if (v > lmax) { lmax = v; lidx = j * 32 + lane; }
        }
        float m0 = 0.f, myv = 0.f; int myi = 0;
        for (int k = 0; k < KK; k++) {
            float bv = lmax; int bi = lidx;
            #pragma unroll
            for (int o = 16; o > 0; o >>= 1) {
                float ov = __shfl_down_sync(0xffffffffu, bv, o);
                int   oi = __shfl_down_sync(0xffffffffu, bi, o);
                if (ov > bv || (ov == bv && oi < bi)) { bv = ov; bi = oi; }
            }
            bv = __shfl_sync(0xffffffffu, bv, 0);
            bi = __shfl_sync(0xffffffffu, bi, 0);
            if (k == 0) m0 = bv;
            if (lane == k) { myv = bv; myi = bi; }
            if ((bi & 31) == lane) {   // owner lane removes & rescans its column
                lrow[bi] = -INFINITY;
                lmax = -INFINITY; lidx = 0x7fffffff;
                #pragma unroll 4
                for (int j = 0; j < 32; j++) {
                    float v = lrow[j * 32 + lane];
                    if (v > lmax) { lmax = v; lidx = j * 32 + lane; }
                }
            }
        }
        float e = expf(myv - m0);
        float sum = e;
        #pragma unroll
        for (int o = 16; o > 0; o >>= 1) sum += __shfl_xor_sync(0xffffffffu, sum, o);
        float wgt = e / sum;
        topw[lane] = wgt; topi[lane] = myi;
        g_topw[b * KK + lane] = wgt; g_topi[b * KK + lane] = myi;
        out_wts[(size_t)b * SS + myi] = wgt;
    }
    __syncthreads();

    // ---- gather read: 256 threads, (d = t&127, half k-split) ----
    {
        const int d = t & 127, half = t >> 7;
        const float* mrow = memory + (size_t)b * SS * DD;
        float a = 0.f;
        #pragma unroll 8
        for (int k = half * 16; k < half * 16 + 16; k++)
            a += topw[k] * mrow[(size_t)topi[k] * DD + d];
        r2[t] = a;
    }
    __syncthreads();
    if (t < 128) {
        float r = r2[t] + r2[t + 128];
        r2[t] = r;
        out_read[(size_t)b * DD + t] = r;
    }
    __syncthreads();

    // ---- gate (warp 0) ----
    if (t < 32) {
        const float* lat = latent + (size_t)b * HH;
        float gl = 0.f, dl = 0.f, pl = 0.f;
        #pragma unroll 4
        for (int j = 0; j < 32; j++) {
            int h = j * 32 + lane;
            float lv = lat[h];
            gl += lv * wgw[h]; dl += lv * dmw[h]; pl += lv * phw[h];
        }
        #pragma unroll
        for (int i = 0; i < 4; i++) {
            float rv = r2[lane * 4 + i];
            gl += rv * wgw[HH + lane * 4 + i];
            dl += rv * dmw[HH + lane * 4 + i];
        }
        #pragma unroll
        for (int o = 16; o > 0; o >>= 1) {
            gl += __shfl_down_sync(0xffffffffu, gl, o);
            dl += __shfl_down_sync(0xffffffffu, dl, o);
            pl += __shfl_down_sync(0xffffffffu, pl, o);
        }
        if (lane == 0) {
            float gate = 1.f / (1.f + expf(-(gl + wgb[0])));
            float dmd  = tanhf(dl + dmb[0]);
            gate = gate * (0.75f + 0.25f * (dmd + 1.f));
            gate = fminf(fmaxf(gate, 0.f), 1.f);
            gate *= 0.5f * (1.f + cosf(pl + phb[0]));
            g_gate[b] = gate;
        }
    }
}

// ---- fixup: rewrite the B*K modified rows (4 rows per warp) ----
__global__ void __launch_bounds__(256)
amt_fixup(const float* __restrict__ memory, float* __restrict__ out)
{
    const int lane = threadIdx.x & 31, wrp = threadIdx.x >> 5;
    const int W  = blockIdx.x * 8 + wrp;   // 0..4095
    const int r0 = W * 4;
    const int b  = r0 >> 5;
    const int k0 = r0 & 31;

    float gate = g_gate[b];
    const float4* v4 = (const float4*)g_value + (size_t)b * 32;
    float4 v = v4[lane];

    int idx[4]; float gw[4]; float4 m[4];
    const float4* m4 = (const float4*)memory;
    #pragma unroll
    for (int j = 0; j < 4; j++) {
        idx[j] = g_topi[b * KK + k0 + j];
        gw[j]  = gate * g_topw[b * KK + k0 + j];
    }
    #pragma unroll
    for (int j = 0; j < 4; j++)
        m[j] = m4[((size_t)b * SS + idx[j]) * 32 + lane];

    float4* o4 = (float4*)(out + (size_t)BB * DD);
    #pragma unroll
    for (int j = 0; j < 4; j++) {
        float4 r = m[j];
        r.x += gw[j] * (v.x - r.x);
        r.y += gw[j] * (v.y - r.y);
        r.z += gw[j] * (v.z - r.z);
        r.w += gw[j] * (v.w - r.w);
        o4[((size_t)b * SS + idx[j]) * 32 + lane] = r;
    }
}

__global__ void amt_dummy() {}

extern "C" void kernel_launch(void* const* d_in, const int* in_sizes, int n_in,
                              void* d_out, int out_size)
{
    const float* latent = (const float*)d_in[0];
    const float* memory = (const float*)d_in[1];
    const float* rqw    = (const float*)d_in[2];
    const float* rqb    = (const float*)d_in[3];
    const float* mkey   = (const float*)d_in[4];
    const float* wgw    = (const float*)d_in[5];
    const float* wgb    = (const float*)d_in[6];
    const float* dmw    = (const float*)d_in[7];
    const float* dmb    = (const float*)d_in[8];
    const float* phw    = (const float*)d_in[9];
    const float* phb    = (const float*)d_in[10];
    const float* wvw    = (const float*)d_in[11];
    const float* wvb    = (const float*)d_in[12];
    float* out = (float*)d_out;

    cudaFuncSetAttribute(amt_stage1, cudaFuncAttributeMaxDynamicSharedMemorySize, 32768);
    cudaFuncSetAttribute(amt_stage2, cudaFuncAttributeMaxDynamicSharedMemorySize, 28672);
    cudaFuncSetAttribute(amt_stage3, cudaFuncAttributeMaxDynamicSharedMemorySize, 5376);

    // 7 launches/call; stage3 sits at index 5 so ncu (-s 5 -c 1) profiles it.
    amt_stage1<<<S1_GEMM + S1_COPY, 256, 32768>>>(latent, memory, rqw, rqb, wvw, wvb, out);
    amt_stage2<<<S2_LOG + S2_COPY, 256, 28672>>>(memory, mkey, out);
    amt_dummy<<<1, 32>>>();
    amt_dummy<<<1, 32>>>();
    amt_dummy<<<1, 32>>>();
    amt_stage3<<<S3_FRONT + S3_COPY, 256, 5376>>>(latent, memory, wgw, wgb,
                                                  dmw, dmb, phw, phb, out);
    amt_fixup<<<512, 256>>>(memory, out);
}